// round 2
// baseline (speedup 1.0000x reference)
#include <cuda_runtime.h>

#define RES   256
#define FEAT  32
#define NPTS  524288

// Transposed planes: [plane][y*RES + x][channel] -> one tap = contiguous 128B.
__device__ float g_pt[3][RES * RES * FEAT];

// (C, H*W) -> (H*W, C) transpose through shared memory tile.
__global__ void transpose_kernel(const float* __restrict__ p0,
                                 const float* __restrict__ p1,
                                 const float* __restrict__ p2) {
    __shared__ float tile[32][33];
    const float* src = (blockIdx.y == 0) ? p0 : (blockIdx.y == 1 ? p1 : p2);
    float* dst = g_pt[blockIdx.y];

    const int hw0 = blockIdx.x * 32;
    const int tx  = threadIdx.x;
    const int ty  = threadIdx.y;

    #pragma unroll
    for (int c = ty; c < FEAT; c += 8)
        tile[c][tx] = src[c * (RES * RES) + hw0 + tx];
    __syncthreads();
    #pragma unroll
    for (int row = ty; row < 32; row += 8)
        dst[(hw0 + row) * FEAT + tx] = tile[tx][row];
}

// 13 samples as indices into the 5-value per-axis coordinate sets
// (multiplier m = (idx-2)*0.5 : idx 0->-1, 1->-0.5, 2->0, 3->+0.5, 4->+1)
__constant__ int c_six[13] = {2, 0, 1, 3, 4, 2, 2, 2, 2, 3, 3, 1, 1};
__constant__ int c_siy[13] = {2, 2, 2, 2, 2, 0, 1, 3, 4, 3, 1, 3, 1};

// 8 lanes per point (float4 channel groups), 4 points per warp.
__global__ void __launch_bounds__(256, 3) sample_kernel(
    const float* __restrict__ pts,
    const float* __restrict__ scales,
    const float* __restrict__ aabb,
    float* __restrict__ out)
{
    const int tid  = blockIdx.x * blockDim.x + threadIdx.x;
    const int lane = tid & 31;
    const int grp  = lane >> 3;
    const int cg   = lane & 7;
    const int p    = (tid >> 5) * 4 + grp;

    const float a00 = aabb[0], a01 = aabb[1], a02 = aabb[2];
    const float a10 = aabb[3], a11 = aabb[4], a12 = aabb[5];

    const float px = pts[p * 3 + 0];
    const float py = pts[p * 3 + 1];
    const float pz = pts[p * 3 + 2];

    float n[3];
    n[0] = (px - a00) * (2.0f / (a10 - a00)) - 1.0f;
    n[1] = (py - a01) * (2.0f / (a11 - a01)) - 1.0f;
    n[2] = (pz - a02) * (2.0f / (a12 - a02)) - 1.0f;

    float s[3];
    s[0] = scales[p * 3 + 0];
    s[1] = scales[p * 3 + 1];
    s[2] = scales[p * 3 + 2];

    const int qidx[3] = {0, 0, 1};
    const int ridx[3] = {1, 2, 2};

    float4 result;
    result.x = 1.0f; result.y = 1.0f; result.z = 1.0f; result.w = 1.0f;

    #pragma unroll
    for (int pl = 0; pl < 3; pl++) {
        const float bx = n[qidx[pl]];
        const float by = n[ridx[pl]];
        const float sx = s[qidx[pl]];
        const float sy = s[ridx[pl]];
        const float4* __restrict__ base = ((const float4*)g_pt[pl]) + cg;

        // per-axis coordinate sets: 5 distinct values per axis
        float xw[5], yw[5];
        int   xo0[5], xo1[5], yo0[5], yo1[5];
        #pragma unroll
        for (int k = 0; k < 5; k++) {
            const float m  = (float)(k - 2) * 0.5f;

            const float gx = fmaf(sx, m, bx);
            float cx = fminf(fmaxf(fmaf(gx, 127.5f, 127.5f), 0.0f), 255.0f);
            const float x0f = floorf(cx);
            xw[k] = cx - x0f;
            const int x0 = (int)x0f;
            xo0[k] = x0 * (FEAT / 4);
            xo1[k] = min(x0 + 1, RES - 1) * (FEAT / 4);

            const float gy = fmaf(sy, m, by);
            float cy = fminf(fmaxf(fmaf(gy, 127.5f, 127.5f), 0.0f), 255.0f);
            const float y0f = floorf(cy);
            yw[k] = cy - y0f;
            const int y0 = (int)y0f;
            yo0[k] = y0 * (RES * FEAT / 4);
            yo1[k] = min(y0 + 1, RES - 1) * (RES * FEAT / 4);
        }

        float4 acc;
        acc.x = 0.0f; acc.y = 0.0f; acc.z = 0.0f; acc.w = 0.0f;

        #pragma unroll
        for (int smp = 0; smp < 13; smp++) {
            const int ax = c_six[smp];
            const int ay = c_siy[smp];

            const float4 f00 = base[yo0[ay] + xo0[ax]];
            const float4 f10 = base[yo0[ay] + xo1[ax]];
            const float4 f01 = base[yo1[ay] + xo0[ax]];
            const float4 f11 = base[yo1[ay] + xo1[ax]];

            const float wx  = xw[ax];
            const float wy  = yw[ay];
            const float w11 = wx * wy;
            const float w10 = wx - w11;
            const float w01 = wy - w11;
            const float w00 = 1.0f - wx - w01;

            acc.x += f00.x * w00 + f10.x * w10 + f01.x * w01 + f11.x * w11;
            acc.y += f00.y * w00 + f10.y * w10 + f01.y * w01 + f11.y * w11;
            acc.z += f00.z * w00 + f10.z * w10 + f01.z * w01 + f11.z * w11;
            acc.w += f00.w * w00 + f10.w * w10 + f01.w * w01 + f11.w * w11;
        }

        const float inv13 = 1.0f / 13.0f;
        result.x *= acc.x * inv13;
        result.y *= acc.y * inv13;
        result.z *= acc.z * inv13;
        result.w *= acc.w * inv13;
    }

    ((float4*)out)[p * (FEAT / 4) + cg] = result;
}

extern "C" void kernel_launch(void* const* d_in, const int* in_sizes, int n_in,
                              void* d_out, int out_size) {
    (void)in_sizes; (void)n_in; (void)out_size;
    const float* pts    = (const float*)d_in[0];
    const float* scales = (const float*)d_in[2];
    const float* p0     = (const float*)d_in[3];
    const float* p1     = (const float*)d_in[4];
    const float* p2     = (const float*)d_in[5];
    const float* aabb   = (const float*)d_in[6];
    float* out          = (float*)d_out;

    dim3 tb(32, 8), tg(RES * RES / 32, 3);
    transpose_kernel<<<tg, tb>>>(p0, p1, p2);

    const int total_threads = NPTS * 8;
    sample_kernel<<<total_threads / 256, 256>>>(pts, scales, aabb, out);
}

// round 3
// speedup vs baseline: 1.3145x; 1.3145x over previous
#include <cuda_runtime.h>

#define RES   256
#define FEAT  32
#define NPTS  524288

// Transposed planes: [plane][y*RES + x][channel] -> one tap = contiguous 128B.
__device__ float g_pt[3][RES * RES * FEAT];

// (C, H*W) -> (H*W, C) transpose through shared memory tile.
__global__ void transpose_kernel(const float* __restrict__ p0,
                                 const float* __restrict__ p1,
                                 const float* __restrict__ p2) {
    __shared__ float tile[32][33];
    const float* src = (blockIdx.y == 0) ? p0 : (blockIdx.y == 1 ? p1 : p2);
    float* dst = g_pt[blockIdx.y];

    const int hw0 = blockIdx.x * 32;
    const int tx  = threadIdx.x;
    const int ty  = threadIdx.y;

    #pragma unroll
    for (int c = ty; c < FEAT; c += 8)
        tile[c][tx] = src[c * (RES * RES) + hw0 + tx];
    __syncthreads();
    #pragma unroll
    for (int row = ty; row < 32; row += 8)
        dst[(hw0 + row) * FEAT + tx] = tile[tx][row];
}

// 13 samples -> per-axis index (compile-time foldable after unroll).
// multiplier m = (idx-2)*0.5 : idx 0->-1, 1->-0.5, 2->0, 3->+0.5, 4->+1
__host__ __device__ constexpr int SIX(int s) {
    constexpr int t[13] = {2, 0, 1, 3, 4, 2, 2, 2, 2, 3, 3, 1, 1};
    return t[s];
}
__host__ __device__ constexpr int SIY(int s) {
    constexpr int t[13] = {2, 2, 2, 2, 2, 0, 1, 3, 4, 3, 1, 3, 1};
    return t[s];
}

// 8 lanes per point (float4 channel groups), 4 points per warp.
__global__ void __launch_bounds__(256, 3) sample_kernel(
    const float* __restrict__ pts,
    const float* __restrict__ scales,
    const float* __restrict__ aabb,
    float* __restrict__ out)
{
    const int tid  = blockIdx.x * blockDim.x + threadIdx.x;
    const int lane = tid & 31;
    const int grp  = lane >> 3;
    const int cg   = lane & 7;
    const int p    = (tid >> 5) * 4 + grp;

    const float a00 = aabb[0], a01 = aabb[1], a02 = aabb[2];
    const float a10 = aabb[3], a11 = aabb[4], a12 = aabb[5];

    const float px = pts[p * 3 + 0];
    const float py = pts[p * 3 + 1];
    const float pz = pts[p * 3 + 2];

    float n[3];
    n[0] = (px - a00) * (2.0f / (a10 - a00)) - 1.0f;
    n[1] = (py - a01) * (2.0f / (a11 - a01)) - 1.0f;
    n[2] = (pz - a02) * (2.0f / (a12 - a02)) - 1.0f;

    float s[3];
    s[0] = scales[p * 3 + 0];
    s[1] = scales[p * 3 + 1];
    s[2] = scales[p * 3 + 2];

    const int qidx[3] = {0, 0, 1};
    const int ridx[3] = {1, 2, 2};

    float4 result;
    result.x = 1.0f; result.y = 1.0f; result.z = 1.0f; result.w = 1.0f;

    #pragma unroll
    for (int pl = 0; pl < 3; pl++) {
        const float bx = n[qidx[pl]];
        const float by = n[ridx[pl]];
        const float sx = s[qidx[pl]];
        const float sy = s[ridx[pl]];
        const float4* __restrict__ base = ((const float4*)g_pt[pl]) + cg;

        // per-axis coordinate sets: 5 distinct values per axis, all regs
        float xw[5], yw[5];
        int   xo0[5], xo1[5], yo0[5], yo1[5];
        #pragma unroll
        for (int k = 0; k < 5; k++) {
            const float m  = (float)(k - 2) * 0.5f;

            const float gx = fmaf(sx, m, bx);
            float cx = fminf(fmaxf(fmaf(gx, 127.5f, 127.5f), 0.0f), 255.0f);
            const float x0f = floorf(cx);
            xw[k] = cx - x0f;
            const int x0 = (int)x0f;
            xo0[k] = x0 * (FEAT / 4);
            xo1[k] = min(x0 + 1, RES - 1) * (FEAT / 4);

            const float gy = fmaf(sy, m, by);
            float cy = fminf(fmaxf(fmaf(gy, 127.5f, 127.5f), 0.0f), 255.0f);
            const float y0f = floorf(cy);
            yw[k] = cy - y0f;
            const int y0 = (int)y0f;
            yo0[k] = y0 * (RES * FEAT / 4);
            yo1[k] = min(y0 + 1, RES - 1) * (RES * FEAT / 4);
        }

        float4 acc;
        acc.x = 0.0f; acc.y = 0.0f; acc.z = 0.0f; acc.w = 0.0f;

        #pragma unroll
        for (int smp = 0; smp < 13; smp++) {
            const int ax = SIX(smp);   // compile-time after unroll
            const int ay = SIY(smp);   // -> xw[ax] etc. stay in registers

            const float4 f00 = base[yo0[ay] + xo0[ax]];
            const float4 f10 = base[yo0[ay] + xo1[ax]];
            const float4 f01 = base[yo1[ay] + xo0[ax]];
            const float4 f11 = base[yo1[ay] + xo1[ax]];

            const float wx  = xw[ax];
            const float wy  = yw[ay];
            const float w11 = wx * wy;
            const float w10 = wx - w11;
            const float w01 = wy - w11;
            const float w00 = 1.0f - wx - w01;

            acc.x += f00.x * w00 + f10.x * w10 + f01.x * w01 + f11.x * w11;
            acc.y += f00.y * w00 + f10.y * w10 + f01.y * w01 + f11.y * w11;
            acc.z += f00.z * w00 + f10.z * w10 + f01.z * w01 + f11.z * w11;
            acc.w += f00.w * w00 + f10.w * w10 + f01.w * w01 + f11.w * w11;
        }

        const float inv13 = 1.0f / 13.0f;
        result.x *= acc.x * inv13;
        result.y *= acc.y * inv13;
        result.z *= acc.z * inv13;
        result.w *= acc.w * inv13;
    }

    ((float4*)out)[p * (FEAT / 4) + cg] = result;
}

extern "C" void kernel_launch(void* const* d_in, const int* in_sizes, int n_in,
                              void* d_out, int out_size) {
    (void)in_sizes; (void)n_in; (void)out_size;
    const float* pts    = (const float*)d_in[0];
    const float* scales = (const float*)d_in[2];
    const float* p0     = (const float*)d_in[3];
    const float* p1     = (const float*)d_in[4];
    const float* p2     = (const float*)d_in[5];
    const float* aabb   = (const float*)d_in[6];
    float* out          = (float*)d_out;

    dim3 tb(32, 8), tg(RES * RES / 32, 3);
    transpose_kernel<<<tg, tb>>>(p0, p1, p2);

    const int total_threads = NPTS * 8;
    sample_kernel<<<total_threads / 256, 256>>>(pts, scales, aabb, out);
}

// round 4
// speedup vs baseline: 2.3744x; 1.8063x over previous
#include <cuda_runtime.h>
#include <cuda_fp16.h>

#define RES   256
#define FEAT  32
#define NPTS  524288

// Transposed fp16 planes: [plane][y*RES + x][channel] -> one texel = 64B.
__device__ __half g_ph[3][RES * RES * FEAT];   // 12 MB

// (C, H*W) fp32 -> (H*W, C) fp16 transpose through shared tile.
__global__ void transpose_kernel(const float* __restrict__ p0,
                                 const float* __restrict__ p1,
                                 const float* __restrict__ p2) {
    __shared__ float tile[32][33];
    const float* src = (blockIdx.y == 0) ? p0 : (blockIdx.y == 1 ? p1 : p2);
    __half* dst = g_ph[blockIdx.y];

    const int hw0 = blockIdx.x * 32;
    const int tx  = threadIdx.x;
    const int ty  = threadIdx.y;

    #pragma unroll
    for (int c = ty; c < FEAT; c += 8)
        tile[c][tx] = src[c * (RES * RES) + hw0 + tx];
    __syncthreads();
    #pragma unroll
    for (int row = ty; row < 32; row += 8)
        dst[(hw0 + row) * FEAT + tx] = __float2half(tile[tx][row]);
}

// 13 samples -> per-axis index (compile-time after unroll).
__host__ __device__ constexpr int SIX(int s) {
    constexpr int t[13] = {2, 0, 1, 3, 4, 2, 2, 2, 2, 3, 3, 1, 1};
    return t[s];
}
__host__ __device__ constexpr int SIY(int s) {
    constexpr int t[13] = {2, 2, 2, 2, 2, 0, 1, 3, 4, 3, 1, 3, 1};
    return t[s];
}

// 4 lanes per point (8 channels each as 4x half2), 8 points per warp.
__global__ void __launch_bounds__(256, 3) sample_kernel(
    const float* __restrict__ pts,
    const float* __restrict__ scales,
    const float* __restrict__ aabb,
    float* __restrict__ out)
{
    const int tid  = blockIdx.x * blockDim.x + threadIdx.x;
    const int lane = tid & 31;
    const int grp  = lane >> 2;        // point within warp (0..7)
    const int cg   = lane & 3;         // channel group (0..3), 8 channels
    const int p    = (tid >> 5) * 8 + grp;

    const float a00 = aabb[0], a01 = aabb[1], a02 = aabb[2];
    const float a10 = aabb[3], a11 = aabb[4], a12 = aabb[5];

    const float px = pts[p * 3 + 0];
    const float py = pts[p * 3 + 1];
    const float pz = pts[p * 3 + 2];

    float n[3];
    n[0] = (px - a00) * (2.0f / (a10 - a00)) - 1.0f;
    n[1] = (py - a01) * (2.0f / (a11 - a01)) - 1.0f;
    n[2] = (pz - a02) * (2.0f / (a12 - a02)) - 1.0f;

    float s[3];
    s[0] = scales[p * 3 + 0];
    s[1] = scales[p * 3 + 1];
    s[2] = scales[p * 3 + 2];

    const int qidx[3] = {0, 0, 1};
    const int ridx[3] = {1, 2, 2};

    float res[8];
    #pragma unroll
    for (int j = 0; j < 8; j++) res[j] = 1.0f;

    #pragma unroll
    for (int pl = 0; pl < 3; pl++) {
        const float bx = n[qidx[pl]];
        const float by = n[ridx[pl]];
        const float sx = s[qidx[pl]];
        const float sy = s[ridx[pl]];
        // texel stride = 4 uint4; this lane's 16B slice = +cg
        const uint4* __restrict__ base = ((const uint4*)g_ph[pl]) + cg;

        // per-axis coordinate sets (5 values each), all in registers
        float xw[5], yw[5];
        int   xo0[5], xo1[5], yo0[5], yo1[5];
        #pragma unroll
        for (int k = 0; k < 5; k++) {
            const float m = (float)(k - 2) * 0.5f;

            const float gx = fmaf(sx, m, bx);
            float cx = fminf(fmaxf(fmaf(gx, 127.5f, 127.5f), 0.0f), 255.0f);
            const float x0f = floorf(cx);
            xw[k] = cx - x0f;
            const int x0 = (int)x0f;
            xo0[k] = x0 * 4;
            xo1[k] = min(x0 + 1, RES - 1) * 4;

            const float gy = fmaf(sy, m, by);
            float cy = fminf(fmaxf(fmaf(gy, 127.5f, 127.5f), 0.0f), 255.0f);
            const float y0f = floorf(cy);
            yw[k] = cy - y0f;
            const int y0 = (int)y0f;
            yo0[k] = y0 * (RES * 4);
            yo1[k] = min(y0 + 1, RES - 1) * (RES * 4);
        }

        float acc[8];
        #pragma unroll
        for (int j = 0; j < 8; j++) acc[j] = 0.0f;

        #pragma unroll
        for (int smp = 0; smp < 13; smp++) {
            const int ax = SIX(smp);
            const int ay = SIY(smp);

            const uint4 q00 = base[yo0[ay] + xo0[ax]];
            const uint4 q10 = base[yo0[ay] + xo1[ax]];
            const uint4 q01 = base[yo1[ay] + xo0[ax]];
            const uint4 q11 = base[yo1[ay] + xo1[ax]];

            const float wx  = xw[ax];
            const float wy  = yw[ay];
            const float w11 = wx * wy;
            const float w10 = wx - w11;
            const float w01 = wy - w11;
            const float w00 = 1.0f - wx - w01;

            const __half2 h00 = __float2half2_rn(w00);
            const __half2 h10 = __float2half2_rn(w10);
            const __half2 h01 = __float2half2_rn(w01);
            const __half2 h11 = __float2half2_rn(w11);

            const unsigned int* u00 = &q00.x;
            const unsigned int* u10 = &q10.x;
            const unsigned int* u01 = &q01.x;
            const unsigned int* u11 = &q11.x;

            #pragma unroll
            for (int j = 0; j < 4; j++) {
                __half2 f00 = *reinterpret_cast<const __half2*>(&u00[j]);
                __half2 f10 = *reinterpret_cast<const __half2*>(&u10[j]);
                __half2 f01 = *reinterpret_cast<const __half2*>(&u01[j]);
                __half2 f11 = *reinterpret_cast<const __half2*>(&u11[j]);

                __half2 hsum = __hfma2(f00, h00,
                                __hfma2(f10, h10,
                                 __hfma2(f01, h01,
                                  __hmul2(f11, h11))));
                const float2 v = __half22float2(hsum);
                acc[j * 2 + 0] += v.x;
                acc[j * 2 + 1] += v.y;
            }
        }

        const float inv13 = 1.0f / 13.0f;
        #pragma unroll
        for (int j = 0; j < 8; j++)
            res[j] *= acc[j] * inv13;
    }

    float4 o0, o1;
    o0.x = res[0]; o0.y = res[1]; o0.z = res[2]; o0.w = res[3];
    o1.x = res[4]; o1.y = res[5]; o1.z = res[6]; o1.w = res[7];
    ((float4*)out)[p * 8 + cg * 2 + 0] = o0;
    ((float4*)out)[p * 8 + cg * 2 + 1] = o1;
}

extern "C" void kernel_launch(void* const* d_in, const int* in_sizes, int n_in,
                              void* d_out, int out_size) {
    (void)in_sizes; (void)n_in; (void)out_size;
    const float* pts    = (const float*)d_in[0];
    const float* scales = (const float*)d_in[2];
    const float* p0     = (const float*)d_in[3];
    const float* p1     = (const float*)d_in[4];
    const float* p2     = (const float*)d_in[5];
    const float* aabb   = (const float*)d_in[6];
    float* out          = (float*)d_out;

    dim3 tb(32, 8), tg(RES * RES / 32, 3);
    transpose_kernel<<<tg, tb>>>(p0, p1, p2);

    const int total_threads = NPTS * 4;   // 4 lanes per point
    sample_kernel<<<total_threads / 256, 256>>>(pts, scales, aabb, out);
}

// round 5
// speedup vs baseline: 2.4928x; 1.0499x over previous
#include <cuda_runtime.h>
#include <cuda_fp16.h>

#define RES   256
#define FEAT  32
#define NPTS  524288
#define NBA   64
#define NBINS (NBA * NBA * NBA)   // 262144

// Transposed fp16 planes: [plane][y*RES + x][channel] -> one texel = 64B.
__device__ __half  g_ph[3][RES * RES * FEAT];    // 12 MB
__device__ unsigned g_binid[NPTS];
__device__ unsigned g_count[NBINS];
__device__ unsigned g_cursor[NBINS];
__device__ unsigned g_offset[NBINS];
__device__ unsigned g_bsum[256];
__device__ float4   g_sdata[NPTS * 2];           // 16 MB: sorted (n0,n1,n2,s0),(s1,s2,orig,-)

// ---------------- plane transpose (C,HW) fp32 -> (HW,C) fp16 ----------------
__global__ void transpose_kernel(const float* __restrict__ p0,
                                 const float* __restrict__ p1,
                                 const float* __restrict__ p2) {
    __shared__ float tile[32][33];
    const float* src = (blockIdx.y == 0) ? p0 : (blockIdx.y == 1 ? p1 : p2);
    __half* dst = g_ph[blockIdx.y];
    const int hw0 = blockIdx.x * 32;
    const int tx = threadIdx.x, ty = threadIdx.y;
    #pragma unroll
    for (int c = ty; c < FEAT; c += 8)
        tile[c][tx] = src[c * (RES * RES) + hw0 + tx];
    __syncthreads();
    #pragma unroll
    for (int row = ty; row < 32; row += 8)
        dst[(hw0 + row) * FEAT + tx] = __float2half(tile[tx][row]);
}

// ---------------- Morton counting sort ----------------
__global__ void zero_kernel() {
    int i = blockIdx.x * blockDim.x + threadIdx.x;
    if (i < NBINS) { g_count[i] = 0; g_cursor[i] = 0; }
}

__device__ __forceinline__ unsigned spread3(unsigned v) {
    unsigned r = (v & 1u);
    r |= (v & 2u)  << 2;
    r |= (v & 4u)  << 4;
    r |= (v & 8u)  << 6;
    r |= (v & 16u) << 8;
    r |= (v & 32u) << 10;
    return r;
}

__global__ void bin_kernel(const float* __restrict__ pts) {
    int p = blockIdx.x * blockDim.x + threadIdx.x;
    if (p >= NPTS) return;
    const float x = pts[p * 3 + 0];
    const float y = pts[p * 3 + 1];
    const float z = pts[p * 3 + 2];
    const float k = (float)NBA / 2.6f;
    int ix = min(NBA - 1, max(0, (int)((x + 1.3f) * k)));
    int iy = min(NBA - 1, max(0, (int)((y + 1.3f) * k)));
    int iz = min(NBA - 1, max(0, (int)((z + 1.3f) * k)));
    unsigned code = spread3(ix) | (spread3(iy) << 1) | (spread3(iz) << 2);
    g_binid[p] = code;
    atomicAdd(&g_count[code], 1u);
}

// exclusive scan over 262144 = 256 blocks x 1024
__global__ void scan_block_kernel() {
    __shared__ unsigned sh[1024];
    const int t = threadIdx.x;
    const int i = blockIdx.x * 1024 + t;
    const unsigned v = g_count[i];
    sh[t] = v;
    __syncthreads();
    #pragma unroll
    for (int d = 1; d < 1024; d <<= 1) {
        unsigned add = (t >= d) ? sh[t - d] : 0u;
        __syncthreads();
        sh[t] += add;
        __syncthreads();
    }
    g_offset[i] = sh[t] - v;                 // local exclusive
    if (t == 1023) g_bsum[blockIdx.x] = sh[t];
}

__global__ void scan_top_kernel() {
    __shared__ unsigned sh[256];
    const int t = threadIdx.x;
    const unsigned v = g_bsum[t];
    sh[t] = v;
    __syncthreads();
    #pragma unroll
    for (int d = 1; d < 256; d <<= 1) {
        unsigned add = (t >= d) ? sh[t - d] : 0u;
        __syncthreads();
        sh[t] += add;
        __syncthreads();
    }
    g_bsum[t] = sh[t] - v;                   // exclusive
}

__global__ void scan_add_kernel() {
    const int i = blockIdx.x * 1024 + threadIdx.x;
    g_offset[i] += g_bsum[blockIdx.x];
}

__global__ void scatter_kernel(const float* __restrict__ pts,
                               const float* __restrict__ scales,
                               const float* __restrict__ aabb) {
    int p = blockIdx.x * blockDim.x + threadIdx.x;
    if (p >= NPTS) return;
    const unsigned bin = g_binid[p];
    const unsigned pos = g_offset[bin] + atomicAdd(&g_cursor[bin], 1u);

    const float a00 = aabb[0], a01 = aabb[1], a02 = aabb[2];
    const float a10 = aabb[3], a11 = aabb[4], a12 = aabb[5];
    const float n0 = (pts[p * 3 + 0] - a00) * (2.0f / (a10 - a00)) - 1.0f;
    const float n1 = (pts[p * 3 + 1] - a01) * (2.0f / (a11 - a01)) - 1.0f;
    const float n2 = (pts[p * 3 + 2] - a02) * (2.0f / (a12 - a02)) - 1.0f;

    g_sdata[pos * 2 + 0] = make_float4(n0, n1, n2, scales[p * 3 + 0]);
    g_sdata[pos * 2 + 1] = make_float4(scales[p * 3 + 1], scales[p * 3 + 2],
                                       __int_as_float(p), 0.0f);
}

// ---------------- main sampling kernel ----------------
__host__ __device__ constexpr int SIX(int s) {
    constexpr int t[13] = {2, 0, 1, 3, 4, 2, 2, 2, 2, 3, 3, 1, 1};
    return t[s];
}
__host__ __device__ constexpr int SIY(int s) {
    constexpr int t[13] = {2, 2, 2, 2, 2, 0, 1, 3, 4, 3, 1, 3, 1};
    return t[s];
}

// 4 lanes per point (8 channels each), 8 sorted points per warp.
__global__ void __launch_bounds__(256, 3) sample_kernel(float* __restrict__ out)
{
    const int tid  = blockIdx.x * blockDim.x + threadIdx.x;
    const int lane = tid & 31;
    const int grp  = lane >> 2;
    const int cg   = lane & 3;
    const int i    = (tid >> 5) * 8 + grp;     // sorted position

    const float4 d0 = g_sdata[i * 2 + 0];
    const float4 d1 = g_sdata[i * 2 + 1];
    const float n[3] = { d0.x, d0.y, d0.z };
    const float s[3] = { d0.w, d1.x, d1.y };
    const int   orig = __float_as_int(d1.z);

    const int qidx[3] = {0, 0, 1};
    const int ridx[3] = {1, 2, 2};

    float res[8];
    #pragma unroll
    for (int j = 0; j < 8; j++) res[j] = 1.0f;

    #pragma unroll
    for (int pl = 0; pl < 3; pl++) {
        const float bx = n[qidx[pl]];
        const float by = n[ridx[pl]];
        const float sx = s[qidx[pl]];
        const float sy = s[ridx[pl]];
        const uint4* __restrict__ base = ((const uint4*)g_ph[pl]) + cg;

        float xw[5], yw[5];
        int   xo0[5], xo1[5], yo0[5], yo1[5];
        #pragma unroll
        for (int k = 0; k < 5; k++) {
            const float m = (float)(k - 2) * 0.5f;

            const float gx = fmaf(sx, m, bx);
            float cx = fminf(fmaxf(fmaf(gx, 127.5f, 127.5f), 0.0f), 255.0f);
            const float x0f = floorf(cx);
            xw[k] = cx - x0f;
            const int x0 = (int)x0f;
            xo0[k] = x0 * 4;
            xo1[k] = min(x0 + 1, RES - 1) * 4;

            const float gy = fmaf(sy, m, by);
            float cy = fminf(fmaxf(fmaf(gy, 127.5f, 127.5f), 0.0f), 255.0f);
            const float y0f = floorf(cy);
            yw[k] = cy - y0f;
            const int y0 = (int)y0f;
            yo0[k] = y0 * (RES * 4);
            yo1[k] = min(y0 + 1, RES - 1) * (RES * 4);
        }

        float acc[8];
        #pragma unroll
        for (int j = 0; j < 8; j++) acc[j] = 0.0f;

        #pragma unroll
        for (int smp = 0; smp < 13; smp++) {
            const int ax = SIX(smp);
            const int ay = SIY(smp);

            const uint4 q00 = base[yo0[ay] + xo0[ax]];
            const uint4 q10 = base[yo0[ay] + xo1[ax]];
            const uint4 q01 = base[yo1[ay] + xo0[ax]];
            const uint4 q11 = base[yo1[ay] + xo1[ax]];

            const float wx  = xw[ax];
            const float wy  = yw[ay];
            const float w11 = wx * wy;
            const float w10 = wx - w11;
            const float w01 = wy - w11;
            const float w00 = 1.0f - wx - w01;

            const __half2 h00 = __float2half2_rn(w00);
            const __half2 h10 = __float2half2_rn(w10);
            const __half2 h01 = __float2half2_rn(w01);
            const __half2 h11 = __float2half2_rn(w11);

            const unsigned int* u00 = &q00.x;
            const unsigned int* u10 = &q10.x;
            const unsigned int* u01 = &q01.x;
            const unsigned int* u11 = &q11.x;

            #pragma unroll
            for (int j = 0; j < 4; j++) {
                __half2 f00 = *reinterpret_cast<const __half2*>(&u00[j]);
                __half2 f10 = *reinterpret_cast<const __half2*>(&u10[j]);
                __half2 f01 = *reinterpret_cast<const __half2*>(&u01[j]);
                __half2 f11 = *reinterpret_cast<const __half2*>(&u11[j]);

                __half2 hsum = __hfma2(f00, h00,
                                __hfma2(f10, h10,
                                 __hfma2(f01, h01,
                                  __hmul2(f11, h11))));
                const float2 v = __half22float2(hsum);
                acc[j * 2 + 0] += v.x;
                acc[j * 2 + 1] += v.y;
            }
        }

        const float inv13 = 1.0f / 13.0f;
        #pragma unroll
        for (int j = 0; j < 8; j++)
            res[j] *= acc[j] * inv13;
    }

    float4 o0, o1;
    o0.x = res[0]; o0.y = res[1]; o0.z = res[2]; o0.w = res[3];
    o1.x = res[4]; o1.y = res[5]; o1.z = res[6]; o1.w = res[7];
    ((float4*)out)[orig * 8 + cg * 2 + 0] = o0;
    ((float4*)out)[orig * 8 + cg * 2 + 1] = o1;
}

extern "C" void kernel_launch(void* const* d_in, const int* in_sizes, int n_in,
                              void* d_out, int out_size) {
    (void)in_sizes; (void)n_in; (void)out_size;
    const float* pts    = (const float*)d_in[0];
    const float* scales = (const float*)d_in[2];
    const float* p0     = (const float*)d_in[3];
    const float* p1     = (const float*)d_in[4];
    const float* p2     = (const float*)d_in[5];
    const float* aabb   = (const float*)d_in[6];
    float* out          = (float*)d_out;

    dim3 tb(32, 8), tg(RES * RES / 32, 3);
    transpose_kernel<<<tg, tb>>>(p0, p1, p2);

    zero_kernel<<<NBINS / 512, 512>>>();
    bin_kernel<<<NPTS / 256, 256>>>(pts);
    scan_block_kernel<<<256, 1024>>>();
    scan_top_kernel<<<1, 256>>>();
    scan_add_kernel<<<256, 1024>>>();
    scatter_kernel<<<NPTS / 256, 256>>>(pts, scales, aabb);

    sample_kernel<<<(NPTS * 4) / 256, 256>>>(out);
}